// round 10
// baseline (speedup 1.0000x reference)
#include <cstdint>
#include <cuda_runtime.h>
#include <cuda_bf16.h>
#include <mma.h>
#include <math.h>

using namespace nvcuda;

// Shapes (fixed): B=16, T=128, L=64, D=768
#define BB 16
#define TT 128
#define LL 64
#define DD 768
#define TG 4
#define NKV (BB * LL * DD)   // 786432
#define NW  (DD * DD)        // 589824

__device__ float g_ktil [NKV];
__device__ float g_vfull[NKV];
__device__ float g_c    [BB * LL];
__device__ float g_G    [NW];
__device__ float g_u    [DD];
__device__ float g_w    [DD];

__device__ __nv_bfloat16 g_keyh[NKV], g_keyl[NKV];
__device__ __nv_bfloat16 g_valh[NKV], g_vall[NKV];
__device__ __nv_bfloat16 g_wvh [NW],  g_wvl [NW];
__device__ __nv_bfloat16 g_wqth[NW],  g_wqtl[NW];   // split of Wq^T
__device__ __nv_bfloat16 g_wkth[NW],  g_wktl[NW];   // split of Wk^T
__device__ __nv_bfloat16 g_Gh  [NW],  g_Gl  [NW];

// ===========================================================================
// helpers
// ===========================================================================
__device__ __forceinline__ void split8(const float* src,
                                       __nv_bfloat16* hi, __nv_bfloat16* lo)
{
    float4 a = *(const float4*)(src);
    float4 b = *(const float4*)(src + 4);
    float v[8] = {a.x, a.y, a.z, a.w, b.x, b.y, b.z, b.w};
    __nv_bfloat16 h[8], l[8];
    #pragma unroll
    for (int i = 0; i < 8; i++) {
        h[i] = __float2bfloat16(v[i]);
        l[i] = __float2bfloat16(v[i] - __bfloat162float(h[i]));
    }
    *(uint4*)hi = *(uint4*)h;
    *(uint4*)lo = *(uint4*)l;
}

__device__ __forceinline__ uint32_t s2u(const void* p) {
    uint32_t a;
    asm("{ .reg .u64 t; cvta.to.shared.u64 t, %1; cvt.u32.u64 %0, t; }"
        : "=r"(a) : "l"(p));
    return a;
}

__device__ __forceinline__ void cp_async16(uint32_t dst, const void* src) {
    asm volatile("cp.async.cg.shared.global [%0], [%1], 16;\n" :: "r"(dst), "l"(src) : "memory");
}

// ===========================================================================
// Merged prep kernel: converts, transposes, matvecs. 256 threads.
//   x <  384 : split key
//   x <  768 : split value
//   x < 1056 : split Wv
//   x < 1632 : transpose-split Wq -> g_wqt{h,l}
//   x < 2208 : transpose-split Wk -> g_wkt{h,l}
//   else     : u = Wq^T bk (3 blocks), w = Wk^T bq (3 blocks)
// ===========================================================================
__global__ void __launch_bounds__(256) prep_kernel(
    const float* __restrict__ key, const float* __restrict__ value,
    const float* __restrict__ Wq, const float* __restrict__ Wk,
    const float* __restrict__ Wv, const float* __restrict__ bq,
    const float* __restrict__ bk)
{
    __shared__ float t[32][33];
    int x = blockIdx.x;

    if (x < 1056) {
        const float* src; __nv_bfloat16 *hi, *lo; int base;
        if (x < 384)      { src = key;   hi = g_keyh; lo = g_keyl; base = x; }
        else if (x < 768) { src = value; hi = g_valh; lo = g_vall; base = x - 384; }
        else              { src = Wv;    hi = g_wvh;  lo = g_wvl;  base = x - 768; }
        int idx = (base * 256 + threadIdx.x) * 8;
        split8(src + idx, hi + idx, lo + idx);
        return;
    }
    if (x < 2208) {
        int i = x - 1056;
        const float* W; __nv_bfloat16 *oh, *ol;
        if (i < 576) { W = Wq; oh = g_wqth; ol = g_wqtl; }
        else         { W = Wk; oh = g_wkth; ol = g_wktl; i -= 576; }
        int d0 = (i % 24) * 32, e0 = (i / 24) * 32;
        int tx = threadIdx.x & 31, ty = threadIdx.x >> 5;
        #pragma unroll
        for (int j = 0; j < 4; j++)
            t[ty + 8 * j][tx] = W[(size_t)(d0 + ty + 8 * j) * DD + e0 + tx];
        __syncthreads();
        #pragma unroll
        for (int j = 0; j < 4; j++) {
            int e = e0 + ty + 8 * j, d = d0 + tx;
            float v = t[tx][ty + 8 * j];
            __nv_bfloat16 h = __float2bfloat16(v);
            oh[(size_t)e * DD + d] = h;
            ol[(size_t)e * DD + d] = __float2bfloat16(v - __bfloat162float(h));
        }
        return;
    }
    {
        int i = x - 2208;                     // 0..5
        int e = (i % 3) * 256 + threadIdx.x;
        const float* W  = (i >= 3) ? Wk : Wq;
        const float* bb = (i >= 3) ? bq : bk;
        float acc = 0.f;
        for (int d = 0; d < DD; d++) acc += W[(size_t)d * DD + e] * bb[d];
        ((i >= 3) ? g_w : g_u)[e] = acc;
    }
}

// x<288: split G -> g_Gh/g_Gl.  x>=288: c[row] = key[row]·w + bq·bk
__global__ void __launch_bounds__(256) splitG_ckey(
    const float* __restrict__ key, const float* __restrict__ bq,
    const float* __restrict__ bk)
{
    int x = blockIdx.x;
    if (x < 288) {
        int idx = (x * 256 + threadIdx.x) * 8;
        split8(g_G + idx, g_Gh + idx, g_Gl + idx);
    } else {
        int row  = (x - 288) * 8 + (threadIdx.x >> 5);
        int lane = threadIdx.x & 31;
        const float* r = key + (size_t)row * DD;
        float acc = 0.f, s0 = 0.f;
        #pragma unroll
        for (int j = 0; j < DD / 32; j++) {
            acc += r[lane + 32 * j] * g_w[lane + 32 * j];
            s0  += bq[lane + 32 * j] * bk[lane + 32 * j];
        }
        #pragma unroll
        for (int o = 16; o; o >>= 1) {
            acc += __shfl_xor_sync(0xffffffffu, acc, o);
            s0  += __shfl_xor_sync(0xffffffffu, s0, o);
        }
        if (lane == 0) g_c[row] = acc + s0;
    }
}

// ===========================================================================
// wmma NT GEMM on pre-split bf16, cp.async double-buffered.
// C[r,n] = sum_k (Ah+Al)[r,k]*(Bh+Bl)[n,k] + bias[n] ~ ah*bh + ah*bl + al*bh
// BM=64, BN=64, BK=32. 128 threads = 4 warps (2x2 of 32x32).
// smem rows padded to 40 bf16 (80B). 44KB dyn smem -> 5 blocks/SM.
// ===========================================================================
#define GSM_AH 0
#define GSM_AL 10240
#define GSM_BH 20480
#define GSM_BL 30720
#define GSM_BT 40960
#define GSM_TOTAL 45056

__device__ __forceinline__ void wgemm_nt(
    const __nv_bfloat16* __restrict__ Ah, const __nv_bfloat16* __restrict__ Al,
    const __nv_bfloat16* __restrict__ Bh, const __nv_bfloat16* __restrict__ Bl,
    const float* __restrict__ bias, float* __restrict__ C,
    int row0, int col0)
{
    extern __shared__ char dsm[];
    __nv_bfloat16* sAh = (__nv_bfloat16*)(dsm + GSM_AH);   // [2][64*40]
    __nv_bfloat16* sAl = (__nv_bfloat16*)(dsm + GSM_AL);
    __nv_bfloat16* sBh = (__nv_bfloat16*)(dsm + GSM_BH);
    __nv_bfloat16* sBl = (__nv_bfloat16*)(dsm + GSM_BL);
    float* biasTile    = (float*)(dsm + GSM_BT);           // [16][64]

    const uint32_t uAh = s2u(sAh), uAl = s2u(sAl), uBh = s2u(sBh), uBl = s2u(sBl);

    const int tid  = threadIdx.x;
    const int warp = tid >> 5;
    const int wr   = (warp >> 1) * 32;   // 0,32
    const int wc   = (warp & 1) * 32;    // 0,32

    for (int idx = tid; idx < 1024; idx += 128) {
        int col = idx & 63;
        biasTile[idx] = bias ? bias[col0 + col] : 0.f;
    }
    __syncthreads();

    wmma::fragment<wmma::accumulator, 16, 16, 16, float> c[2][2];
    #pragma unroll
    for (int i = 0; i < 2; i++)
        #pragma unroll
        for (int j = 0; j < 2; j++)
            wmma::load_matrix_sync(c[i][j], &biasTile[wc + 16 * j], 64,
                                   wmma::mem_row_major);

    // cp.async mapping: 2 threads per row, 32B each, for each of 4 matrices
    const int ar = tid >> 1;          // row 0..63
    const int as = (tid & 1) * 32;    // byte offset within 64B row: 0 or 32

    const __nv_bfloat16* pAh0 = Ah + (size_t)(row0 + ar) * DD + (as >> 1);
    const __nv_bfloat16* pAl0 = Al + (size_t)(row0 + ar) * DD + (as >> 1);
    const __nv_bfloat16* pBh0 = Bh + (size_t)(col0 + ar) * DD + (as >> 1);
    const __nv_bfloat16* pBl0 = Bl + (size_t)(col0 + ar) * DD + (as >> 1);

    #define ISSUE(st) do {                                                   \
        if ((st) < 24) {                                                     \
            int _buf = (st) & 1, _k0 = (st) * 32;                            \
            uint32_t d = (uint32_t)(_buf * 5120 + ar * 80 + as);             \
            cp_async16(uAh + d,      pAh0 + _k0);                            \
            cp_async16(uAh + d + 16, pAh0 + _k0 + 8);                        \
            cp_async16(uAl + d,      pAl0 + _k0);                            \
            cp_async16(uAl + d + 16, pAl0 + _k0 + 8);                        \
            cp_async16(uBh + d,      pBh0 + _k0);                            \
            cp_async16(uBh + d + 16, pBh0 + _k0 + 8);                        \
            cp_async16(uBl + d,      pBl0 + _k0);                            \
            cp_async16(uBl + d + 16, pBl0 + _k0 + 8);                        \
        }                                                                    \
        asm volatile("cp.async.commit_group;\n" ::: "memory");               \
    } while (0)

    ISSUE(0);
    ISSUE(1);

    for (int st = 0; st < 24; st++) {
        asm volatile("cp.async.wait_group 1;\n" ::: "memory");
        __syncthreads();
        const int buf = st & 1;
        const __nv_bfloat16* bAh = sAh + buf * 2560;
        const __nv_bfloat16* bAl = sAl + buf * 2560;
        const __nv_bfloat16* bBh = sBh + buf * 2560;
        const __nv_bfloat16* bBl = sBl + buf * 2560;

        #pragma unroll
        for (int ks = 0; ks < 2; ks++) {
            wmma::fragment<wmma::matrix_a, 16, 16, 16, __nv_bfloat16, wmma::row_major> ah[2], al[2];
            wmma::fragment<wmma::matrix_b, 16, 16, 16, __nv_bfloat16, wmma::col_major> bh[2], bl[2];
            #pragma unroll
            for (int i = 0; i < 2; i++) {
                wmma::load_matrix_sync(ah[i], bAh + (wr + 16 * i) * 40 + ks * 16, 40);
                wmma::load_matrix_sync(al[i], bAl + (wr + 16 * i) * 40 + ks * 16, 40);
            }
            #pragma unroll
            for (int j = 0; j < 2; j++) {
                wmma::load_matrix_sync(bh[j], bBh + (wc + 16 * j) * 40 + ks * 16, 40);
                wmma::load_matrix_sync(bl[j], bBl + (wc + 16 * j) * 40 + ks * 16, 40);
            }
            #pragma unroll
            for (int i = 0; i < 2; i++)
                #pragma unroll
                for (int j = 0; j < 2; j++) {
                    wmma::mma_sync(c[i][j], ah[i], bh[j], c[i][j]);
                    wmma::mma_sync(c[i][j], ah[i], bl[j], c[i][j]);
                    wmma::mma_sync(c[i][j], al[i], bh[j], c[i][j]);
                }
        }
        __syncthreads();
        ISSUE(st + 2);
    }
    #undef ISSUE

    #pragma unroll
    for (int i = 0; i < 2; i++)
        #pragma unroll
        for (int j = 0; j < 2; j++)
            wmma::store_matrix_sync(
                C + (size_t)(row0 + wr + 16 * i) * DD + col0 + wc + 16 * j,
                c[i][j], DD, wmma::mem_row_major);
}

// L1: blocks 0..143 -> G = Wq^T@Wk (768x768); 144..335 -> vfull = value@Wv^T+bv
__global__ void __launch_bounds__(128) wg_L1(const float* __restrict__ bv)
{
    int x = blockIdx.x;
    if (x < 144)
        wgemm_nt(g_wqth, g_wqtl, g_wkth, g_wktl, nullptr, g_G,
                 (x / 12) * 64, (x % 12) * 64);
    else {
        x -= 144;
        wgemm_nt(g_valh, g_vall, g_wvh, g_wvl, bv, g_vfull,
                 (x / 12) * 64, (x % 12) * 64);
    }
}

// L2: ktil = key @ G^T + u  (1024x768), 192 blocks
__global__ void __launch_bounds__(128) wg_L2()
{
    int x = blockIdx.x;
    wgemm_nt(g_keyh, g_keyl, g_Gh, g_Gl, g_u, g_ktil,
             (x / 12) * 64, (x % 12) * 64);
}

// ===========================================================================
// Fused attention (identical to R6 best)
// ===========================================================================
#define STAGE_FLOATS (TG * 8 * 384)
#define STAGE_BYTES  (STAGE_FLOATS * 4)

__global__ void __launch_bounds__(256) attn_kernel(const float* __restrict__ query,
                                                   float* __restrict__ out)
{
    extern __shared__ float sq[];
    __shared__ float s_sc[TG][LL];
    __shared__ float s_attn[TG][LL];

    const int t0   = blockIdx.x * TG;
    const int b    = blockIdx.y;
    const int tid  = threadIdx.x;
    const int wid  = tid >> 5;
    const int lane = tid & 31;

    const float rs = 0.03608439182435161f;

    const uint32_t smq = (uint32_t)__cvta_generic_to_shared(sq);

    const int tt_w  = tid >> 3;
    const int cw_tt = tt_w >> 3;
    const int cw_w  = tt_w & 7;
    const int colb  = tid & 7;

    const float4* kb = (const float4*)g_ktil + (size_t)b * LL * (DD / 4);

    float acc[TG];
    #pragma unroll
    for (int tt = 0; tt < TG; tt++) acc[tt] = 0.f;

    {
        const float* src = query + ((size_t)(b * TT + t0 + cw_tt) * LL + cw_w) * DD;
        uint32_t dst = smq + (uint32_t)(tt_w * 96) * 16;
        #pragma unroll
        for (int j = 0; j < 12; j++) {
            int c4 = colb + 8 * j;
            cp_async16(dst + c4 * 16, src + c4 * 4);
        }
        asm volatile("cp.async.commit_group;\n" ::: "memory");
    }

    float4 k0, k1, k2;
    {
        const float4* krow = kb + (size_t)wid * 192;
        k0 = krow[lane]; k1 = krow[lane + 32]; k2 = krow[lane + 64];
    }

    for (int c = 0; c < 16; c++) {
        float4 n0, n1, n2;
        if (c < 15) {
            const int lg = (c + 1) >> 1, h = (c + 1) & 1;
            const float* src = query +
                ((size_t)(b * TT + t0 + cw_tt) * LL + (lg * 8 + cw_w)) * DD + h * 384;
            uint32_t dst = smq + (uint32_t)(((c + 1) & 1) * STAGE_BYTES)
                               + (uint32_t)(tt_w * 96) * 16;
            #pragma unroll
            for (int j = 0; j < 12; j++) {
                int c4 = colb + 8 * j;
                cp_async16(dst + c4 * 16, src + c4 * 4);
            }
            asm volatile("cp.async.commit_group;\n" ::: "memory");
            const float4* krow = kb + (size_t)(lg * 8 + wid) * 192 + h * 96;
            n0 = krow[lane]; n1 = krow[lane + 32]; n2 = krow[lane + 64];
            asm volatile("cp.async.wait_group 1;\n" ::: "memory");
        } else {
            asm volatile("cp.async.wait_group 0;\n" ::: "memory");
        }
        __syncthreads();

        const int lg = c >> 1, h = c & 1;
        const int l = lg * 8 + wid;
        const float4* sqf = (const float4*)(sq + (c & 1) * STAGE_FLOATS);

        #pragma unroll
        for (int tt = 0; tt < TG; tt++) {
            const float4* qs = sqf + (tt * 8 + wid) * 96;
            float4 q0 = qs[lane], q1 = qs[lane + 32], q2 = qs[lane + 64];
            acc[tt] += q0.x * k0.x + q0.y * k0.y + q0.z * k0.z + q0.w * k0.w
                     + q1.x * k1.x + q1.y * k1.y + q1.z * k1.z + q1.w * k1.w
                     + q2.x * k2.x + q2.y * k2.y + q2.z * k2.z + q2.w * k2.w;
        }

        if (h == 1) {
            #pragma unroll
            for (int tt = 0; tt < TG; tt++) {
                float r = acc[tt];
                #pragma unroll
                for (int o = 16; o; o >>= 1) r += __shfl_xor_sync(0xffffffffu, r, o);
                if (lane == 0) s_sc[tt][l] = (r + g_c[b * LL + l]) * rs;
                acc[tt] = 0.f;
            }
        }
        __syncthreads();

        k0 = n0; k1 = n1; k2 = n2;
    }

    if (wid < TG) {
        float v0 = s_sc[wid][lane], v1 = s_sc[wid][lane + 32];
        float m = fmaxf(v0, v1);
        #pragma unroll
        for (int o = 16; o; o >>= 1) m = fmaxf(m, __shfl_xor_sync(0xffffffffu, m, o));
        float e0 = expf(v0 - m), e1 = expf(v1 - m);
        float s = e0 + e1;
        #pragma unroll
        for (int o = 16; o; o >>= 1) s += __shfl_xor_sync(0xffffffffu, s, o);
        float inv = 1.f / s;
        s_attn[wid][lane]      = e0 * inv;
        s_attn[wid][lane + 32] = e1 * inv;
    }
    __syncthreads();

    const float4* vb = (const float4*)g_vfull + (size_t)b * LL * 192;
    #pragma unroll 1
    for (int l = wid; l < LL; l += 8) {
        const float4* vr = vb + (size_t)l * 192;
        float4 v0 = vr[lane], v1 = vr[lane + 32], v2 = vr[lane + 64],
               v3 = vr[lane + 96], v4 = vr[lane + 128], v5 = vr[lane + 160];
        #pragma unroll
        for (int tt = 0; tt < TG; tt++) {
            const float a = s_attn[tt][l];
            float4* orow = (float4*)out + ((size_t)(b * TT + t0 + tt) * LL + l) * 192;
            orow[lane]       = make_float4(a * v0.x, a * v0.y, a * v0.z, a * v0.w);
            orow[lane + 32]  = make_float4(a * v1.x, a * v1.y, a * v1.z, a * v1.w);
            orow[lane + 64]  = make_float4(a * v2.x, a * v2.y, a * v2.z, a * v2.w);
            orow[lane + 96]  = make_float4(a * v3.x, a * v3.y, a * v3.z, a * v3.w);
            orow[lane + 128] = make_float4(a * v4.x, a * v4.y, a * v4.z, a * v4.w);
            orow[lane + 160] = make_float4(a * v5.x, a * v5.y, a * v5.z, a * v5.w);
        }
    }
}

// ---------------------------------------------------------------------------
extern "C" void kernel_launch(void* const* d_in, const int* in_sizes, int n_in,
                              void* d_out, int out_size)
{
    const float* query = (const float*)d_in[0];
    const float* key   = (const float*)d_in[1];
    const float* value = (const float*)d_in[2];
    const float* Wq    = (const float*)d_in[3];
    const float* bq    = (const float*)d_in[4];
    const float* Wk    = (const float*)d_in[5];
    const float* bk    = (const float*)d_in[6];
    const float* Wv    = (const float*)d_in[7];
    const float* bv    = (const float*)d_in[8];
    float* out = (float*)d_out;

    static int attr_set = 0;
    if (!attr_set) {
        cudaFuncSetAttribute(attn_kernel, cudaFuncAttributeMaxDynamicSharedMemorySize,
                             2 * STAGE_BYTES);
        cudaFuncSetAttribute(wg_L1, cudaFuncAttributeMaxDynamicSharedMemorySize,
                             GSM_TOTAL);
        cudaFuncSetAttribute(wg_L2, cudaFuncAttributeMaxDynamicSharedMemorySize,
                             GSM_TOTAL);
        attr_set = 1;
    }

    prep_kernel<<<2214, 256>>>(key, value, Wq, Wk, Wv, bq, bk);
    wg_L1<<<336, 128, GSM_TOTAL>>>(bv);
    splitG_ckey<<<416, 256>>>(key, bq, bk);
    wg_L2<<<192, 128, GSM_TOTAL>>>();
    attn_kernel<<<dim3(TT / TG, BB), 256, 2 * STAGE_BYTES>>>(query, out);
}